// round 8
// baseline (speedup 1.0000x reference)
#include <cuda_runtime.h>
#include <math.h>

#define BB 2
#define SS 128
#define HH 256
#define CC 8
#define PAD 260        // main-kernel smem row stride (floats, multiple of 4)

// ---------------- scratch (device globals; no allocation allowed) ----------
__device__ float g_z[BB * SS * HH];            // 256 KB
__device__ float g_cumexp[BB * SS * CC];       // 8 KB   [b][s][c]
__device__ float g_cumm[BB * SS * CC * HH];    // 2 MB   [b][s][c][h]

// ---------------------------------------------------------------------------
// Kernel A: z[b,s,h] = relu(memory[b,s,:] . W_w[h,:] + W_b[h])
// grid 512 = (64 s-tiles of 4 rows) x (8 h-tiles of 32); 256 threads.
// ---------------------------------------------------------------------------
__global__ void __launch_bounds__(256) kernelA(const float* __restrict__ memory,
                                               const float* __restrict__ Ww,
                                               const float* __restrict__ Wb)
{
    __shared__ float Msh[4 * HH];    // 4 KB

    int bid = blockIdx.x;
    int st = bid >> 3;               // s-tile 0..63
    int ht = bid & 7;                // h-tile 0..7
    int s0 = st * 4;
    int tid = threadIdx.x;
    int lane = tid & 31, w = tid >> 5;

    {
        int rr = tid >> 6;
        int k4 = tid & 63;
        ((float4*)&Msh[rr * HH])[k4] =
            ((const float4*)&memory[(s0 + rr) * HH])[k4];
    }
    __syncthreads();

    int hl = lane >> 3;              // 0..3
    int kp = lane & 7;               // 0..7
    int h = ht * 32 + w * 4 + hl;

    float acc[4] = {0.0f, 0.0f, 0.0f, 0.0f};

    const float4* wr = (const float4*)&Ww[h * HH];
#pragma unroll
    for (int i = 0; i < 8; i++) {
        float4 wv = wr[i * 8 + kp];          // coalesced across kp
#pragma unroll
        for (int r = 0; r < 4; r++) {
            float4 m = *(const float4*)&Msh[r * HH + i * 32 + kp * 4];
            acc[r] = fmaf(m.x, wv.x,
                     fmaf(m.y, wv.y,
                     fmaf(m.z, wv.z,
                     fmaf(m.w, wv.w, acc[r]))));
        }
    }

#pragma unroll
    for (int r = 0; r < 4; r++) {
        float v = acc[r];
        v += __shfl_xor_sync(0xffffffffu, v, 1);
        v += __shfl_xor_sync(0xffffffffu, v, 2);
        v += __shfl_xor_sync(0xffffffffu, v, 4);
        acc[r] = v;
    }
    if (kp == 0) {
        float bias = Wb[h];
#pragma unroll
        for (int r = 0; r < 4; r++)
            g_z[(s0 + r) * HH + h] = fmaxf(acc[r] + bias, 0.0f);
    }
}

// ---------------------------------------------------------------------------
// Kernel B (fused): grid 128 = (b,c) x 8 h-chunks; 256 threads.
// Phase 1 (tid<128): score = U.z dot, softmax-exp, warp-scan cumsum.
//   (duplicated across the 8 h-chunk blocks of one (b,c) — cheap, saves a
//    kernel launch + gap). cumexp stored by hc==0 blocks only.
// Phase 2 (all 256): cumm[b,s,c,h] for 32 h-lanes x 8 s-groups of 16,
//   running sums + smem prefix; coalesced LDG/STG.
// ---------------------------------------------------------------------------
__global__ void __launch_bounds__(256) kernelB(const float* __restrict__ memory,
                                               const float* __restrict__ Uw)
{
    __shared__ float Ush[HH];
    __shared__ float esh[SS];
    __shared__ float wred[4];
    __shared__ float wsum[4];
    __shared__ float psum[8][32];

    int bid = blockIdx.x;
    int hc = bid & 7;
    int bc = bid >> 3;               // b*CC + c
    int b = bc >> 3;
    int c = bc & 7;
    int tid = threadIdx.x;
    int lane = tid & 31, w = tid >> 5;

    if (tid < 64)
        ((float4*)Ush)[tid] = ((const float4*)(Uw + c * HH))[tid];
    __syncthreads();

    if (tid < SS) {
        float sc = 0.0f;
        const float4* zr = (const float4*)&g_z[(b * SS + tid) * HH];
        const float4* u4 = (const float4*)Ush;
#pragma unroll 8
        for (int k = 0; k < 64; k++) {
            float4 z = zr[k];
            float4 u = u4[k];
            sc += z.x * u.x + z.y * u.y + z.z * u.z + z.w * u.w;
        }
        float m = sc;
#pragma unroll
        for (int o = 16; o > 0; o >>= 1)
            m = fmaxf(m, __shfl_xor_sync(0xffffffffu, m, o));
        if (lane == 0) wred[w] = m;
        __syncwarp();
        // inter-warp max via smem (warps 0..3 only)
        __threadfence_block();
    }
    __syncthreads();
    if (tid < SS) {
        float mx = fmaxf(fmaxf(wred[0], wred[1]), fmaxf(wred[2], wred[3]));
        // recompute sc? no — keep in register: restructure below
        // (sc preserved in the same branch scope via recomputation-free path)
        // NOTE: sc is out of scope here; handled by merging branches below.
        (void)mx;
    }
    // --- redo phase 1 with persistent registers (single branch) ---
    // (The above structure can't keep sc across __syncthreads inside an if;
    //  do it properly:)
    float sc2 = 0.0f;
    if (tid < SS) {
        const float4* zr = (const float4*)&g_z[(b * SS + tid) * HH];
        const float4* u4 = (const float4*)Ush;
#pragma unroll 8
        for (int k = 0; k < 64; k++) {
            float4 z = zr[k];
            float4 u = u4[k];
            sc2 += z.x * u.x + z.y * u.y + z.z * u.z + z.w * u.w;
        }
    }
    __syncthreads();
    if (tid < SS) {
        float mx = fmaxf(fmaxf(wred[0], wred[1]), fmaxf(wred[2], wred[3]));
        float e = expf(sc2 - mx);
        float x = e;
#pragma unroll
        for (int o = 1; o < 32; o <<= 1) {
            float t = __shfl_up_sync(0xffffffffu, x, o);
            if (lane >= o) x += t;
        }
        if (lane == 31) wsum[w] = x;
        esh[tid] = e;
        if (hc == 0) {
            // prefix across warps added after sync below; store e-scan part
        }
        // x + prefix written after next sync
        psum[0][0] = psum[0][0]; // no-op
        // stash x in shared for later combine
        // reuse esh? need e; use a second pass:
    }
    __syncthreads();
    if (hc == 0 && tid < SS) {
        float pre = 0.0f;
        for (int ww = 0; ww < w; ww++) pre += wsum[ww];
        // recompute thread's inclusive warp-scan value from e? cheaper: redo scan
        float x = esh[tid - lane + 0]; // placeholder start
        // simple: recompute inclusive scan of esh within warp
        float v = esh[tid];
        float xx = v;
#pragma unroll
        for (int o = 1; o < 32; o <<= 1) {
            float t = __shfl_up_sync(0xffffffffu, xx, o);
            if (lane >= o) xx += t;
        }
        g_cumexp[(b * SS + tid) * CC + c] = xx + pre;
        (void)x;
    }
    __syncthreads();

    // Phase 2: cumm
    {
        int hl = tid & 31;
        int sg = tid >> 5;           // s-group 0..7
        int h = hc * 32 + hl;
        const float* mp = memory + (size_t)b * SS * HH + h;

        float val[16];
        float run = 0.0f;
#pragma unroll
        for (int k = 0; k < 16; k++) {
            int s = sg * 16 + k;
            run = fmaf(mp[(size_t)s * HH], esh[s], run);
            val[k] = run;
        }
        psum[sg][hl] = run;
        __syncthreads();

        float off = 0.0f;
        for (int t = 0; t < sg; t++) off += psum[t][hl];

        float* op = g_cumm + ((size_t)b * SS * CC + c) * HH + h;
#pragma unroll
        for (int k = 0; k < 16; k++) {
            int s = sg * 16 + k;
            op[(size_t)s * (CC * HH)] = val[k] + off;
        }
    }
}

// ---------------------------------------------------------------------------
// Main kernel:
//   out[b,i,j,c] = (sum_h relu(R[j,h]-P[i,h]) * V[c,h]) / denom + V_b[c]
// grid 256 = b(2) x i-tile(4 of 32) x j-tile(8 of 16) x c-pair(4); 256 thr.
// Single wave at occupancy 2. warps: 2 local c x 4 h-quarters.
// lanes: 8 ilane x 4 jlane; per-lane tile 4i x 4j (16 accumulators).
// LDS per h-quad: 4 P + 4 R + 1 V = 9 for 64 updates (was 7/32).
// ---------------------------------------------------------------------------
__global__ void __launch_bounds__(256, 2) kernelMain(const float* __restrict__ Vw,
                                                     const float* __restrict__ Vb,
                                                     float* __restrict__ out)
{
    extern __shared__ float sm[];
    float* Psh = sm;                   // 64 * PAD = 16640 (2c x 32 i-rows)
    float* Rsh = sm + 16640;           // 32 * PAD = 8320  (2c x 16 j-rows)
    float* Vsh = sm + 24960;           // 512   (total 25472 fl = 101888 B)
    float* red = sm;                   // aliases Psh; 8 x 544 = 4352 fl

    int bid = blockIdx.x;
    int cpair = bid & 3;
    int jt = (bid >> 2) & 7;
    int it = (bid >> 5) & 3;
    int b = bid >> 7;
    int i0 = it * 32, j0 = jt * 16, cbase = cpair * 2;
    int tid = threadIdx.x;

    // stage V (2 c x 256 h)
    if (tid < 128)
        *(float4*)&Vsh[tid * 4] = *(const float4*)&Vw[cbase * HH + tid * 4];

    // stage P: 64 rows (2c x 32), 8 threads/row, 2 passes
    {
        int c4 = tid & 7;
#pragma unroll
        for (int pass = 0; pass < 2; pass++) {
            int rr = (tid >> 3) + pass * 32;   // 0..63
            int cl = rr >> 5, ir = rr & 31;
            int gi = i0 + ir;
            const float* srcP = (gi == 0) ? (const float*)0
                : &g_cumm[((size_t)(b * SS + gi - 1) * CC + cbase + cl) * HH];
            float* dstP = &Psh[rr * PAD];
#pragma unroll
            for (int k = 0; k < 8; k++) {
                int h = c4 * 4 + k * 32;
                float4 pv = srcP ? *(const float4*)&srcP[h]
                                 : make_float4(0.f, 0.f, 0.f, 0.f);
                *(float4*)&dstP[h] = pv;
            }
        }
        // stage R: 32 rows (2c x 16), 1 pass
        int rr = tid >> 3;
        int cl = rr >> 4, jr = rr & 15;
        int gj = j0 + jr;
        const float* srcR = &g_cumm[((size_t)(b * SS + gj) * CC + cbase + cl) * HH];
        float* dstR = &Rsh[rr * PAD];
#pragma unroll
        for (int k = 0; k < 8; k++) {
            int h = c4 * 4 + k * 32;
            *(float4*)&dstR[h] = *(const float4*)&srcR[h];
        }
    }
    __syncthreads();

    int lane = tid & 31, w = tid >> 5;
    int cl = w & 1;                    // local c
    int hq = w >> 1;                   // h quarter 0..3
    int ilane = lane >> 2;             // 0..7
    int jlane = lane & 3;              // 0..3

    const float* Pb = &Psh[(cl * 32) * PAD];
    const float* Rb = &Rsh[(cl * 16) * PAD];
    const float* Vp = &Vsh[cl * HH];

    float acc[4][4];
#pragma unroll
    for (int ii = 0; ii < 4; ii++)
#pragma unroll
        for (int jj = 0; jj < 4; jj++) acc[ii][jj] = 0.0f;

    int hbase = hq * 64;
#pragma unroll 4
    for (int hh = 0; hh < 64; hh += 4) {
        int h = hbase + hh;
        float4 v = *(const float4*)&Vp[h];
        float4 p[4];
#pragma unroll
        for (int ii = 0; ii < 4; ii++)
            p[ii] = *(const float4*)&Pb[(ilane + 8 * ii) * PAD + h];
#pragma unroll
        for (int jj = 0; jj < 4; jj++) {
            float4 r = *(const float4*)&Rb[(jlane + 4 * jj) * PAD + h];
#pragma unroll
            for (int ii = 0; ii < 4; ii++) {
                float t;
                t = fmaxf(r.x - p[ii].x, 0.0f); acc[ii][jj] = fmaf(t, v.x, acc[ii][jj]);
                t = fmaxf(r.y - p[ii].y, 0.0f); acc[ii][jj] = fmaf(t, v.y, acc[ii][jj]);
                t = fmaxf(r.z - p[ii].z, 0.0f); acc[ii][jj] = fmaf(t, v.z, acc[ii][jj]);
                t = fmaxf(r.w - p[ii].w, 0.0f); acc[ii][jj] = fmaf(t, v.w, acc[ii][jj]);
            }
        }
    }

    __syncthreads();   // all warps done reading Psh before red overwrites it

    // partials: red[(hq*2+cl)*544 + i*17 + j]
#pragma unroll
    for (int ii = 0; ii < 4; ii++)
#pragma unroll
        for (int jj = 0; jj < 4; jj++) {
            int i = ilane + 8 * ii;
            int j = jlane + 4 * jj;
            red[(hq * 2 + cl) * 544 + i * 17 + j] = acc[ii][jj];
        }
    __syncthreads();

    // epilogue: thread tid handles (c0,c1) for (i, j) and (i+16, j)
    {
        int i = tid >> 4;              // 0..15
        int j = tid & 15;
#pragma unroll
        for (int rep = 0; rep < 2; rep++) {
            int ir = i + 16 * rep;
            int o = ir * 17 + j;
            float s0 = red[o] + red[1088 + o] + red[2176 + o] + red[3264 + o];
            int o2 = o + 544;
            float s1 = red[o2] + red[1088 + o2] + red[2176 + o2] + red[3264 + o2];
            int gi = i0 + ir, gj = j0 + j;
            float cej0 = g_cumexp[(b * SS + gj) * CC + cbase];
            float cej1 = g_cumexp[(b * SS + gj) * CC + cbase + 1];
            float cei0 = 0.0f, cei1 = 0.0f;
            if (gi > 0) {
                cei0 = g_cumexp[(b * SS + gi - 1) * CC + cbase];
                cei1 = g_cumexp[(b * SS + gi - 1) * CC + cbase + 1];
            }
            float d0 = cej0 - cei0; if (d0 <= 1e-6f) d0 = 100.0f;
            float d1 = cej1 - cei1; if (d1 <= 1e-6f) d1 = 100.0f;
            float2 res;
            res.x = __fdividef(s0, d0) + Vb[cbase];
            res.y = __fdividef(s1, d1) + Vb[cbase + 1];
            *(float2*)&out[((size_t)(b * SS + gi) * SS + gj) * CC + cbase] = res;
        }
    }
}

// ---------------------------------------------------------------------------
extern "C" void kernel_launch(void* const* d_in, const int* in_sizes, int n_in,
                              void* d_out, int out_size)
{
    (void)in_sizes; (void)n_in; (void)out_size;
    const float* memory = (const float*)d_in[0];
    const float* Ww     = (const float*)d_in[1];
    const float* Wb     = (const float*)d_in[2];
    const float* Uw     = (const float*)d_in[3];
    const float* Vw     = (const float*)d_in[4];
    const float* Vb     = (const float*)d_in[5];
    float* out          = (float*)d_out;

    cudaFuncSetAttribute(kernelMain, cudaFuncAttributeMaxDynamicSharedMemorySize,
                         25472 * 4);

    kernelA<<<512, 256>>>(memory, Ww, Wb);
    kernelB<<<128, 256>>>(memory, Uw);
    kernelMain<<<256, 256, 25472 * 4>>>(Vw, Vb, out);
}

// round 9
// speedup vs baseline: 1.1270x; 1.1270x over previous
#include <cuda_runtime.h>
#include <math.h>

#define BB 2
#define SS 128
#define HH 256
#define CC 8
#define PAD 260        // main-kernel smem row stride (floats, multiple of 4)

// ---------------- scratch (device globals; no allocation allowed) ----------
__device__ float g_z[BB * SS * HH];            // 256 KB
__device__ float g_e[BB * CC * SS];            // 8 KB   [b][c][s]
__device__ float g_cumexp[BB * SS * CC];       // 8 KB   [b][s][c]
__device__ float g_cumm[BB * SS * CC * HH];    // 2 MB   [b][s][c][h]

// ---------------------------------------------------------------------------
// Kernel A: z[b,s,h] = relu(memory[b,s,:] . W_w[h,:] + W_b[h])
// grid 256 = (32 s-tiles of 8 rows) x (8 h-tiles of 32); 256 threads.
// Warp covers 4 h; lane = hl*8 + kp. W reads coalesced (4x128B per warp).
// 8 rows/thread doubles FMA-per-LDS and halves W L2 traffic vs 4-row tiles.
// ---------------------------------------------------------------------------
__global__ void __launch_bounds__(256) kernelA(const float* __restrict__ memory,
                                               const float* __restrict__ Ww,
                                               const float* __restrict__ Wb)
{
    __shared__ float Msh[8 * HH];    // 8 KB

    int bid = blockIdx.x;
    int st = bid >> 3;               // s-tile 0..31
    int ht = bid & 7;                // h-tile 0..7
    int s0 = st * 8;
    int tid = threadIdx.x;
    int lane = tid & 31, w = tid >> 5;

    // stage 8 memory rows (512 float4, 2 per thread)
#pragma unroll
    for (int t = 0; t < 2; t++) {
        int idx = tid + t * 256;
        int rr = idx >> 6;
        int k4 = idx & 63;
        ((float4*)&Msh[rr * HH])[k4] =
            ((const float4*)&memory[(s0 + rr) * HH])[k4];
    }
    __syncthreads();

    int hl = lane >> 3;              // 0..3
    int kp = lane & 7;               // 0..7
    int h = ht * 32 + w * 4 + hl;

    float acc[8];
#pragma unroll
    for (int r = 0; r < 8; r++) acc[r] = 0.0f;

    const float4* wr = (const float4*)&Ww[h * HH];
#pragma unroll
    for (int i = 0; i < 8; i++) {
        float4 wv = wr[i * 8 + kp];          // coalesced across kp
#pragma unroll
        for (int r = 0; r < 8; r++) {
            float4 m = *(const float4*)&Msh[r * HH + i * 32 + kp * 4];
            acc[r] = fmaf(m.x, wv.x,
                     fmaf(m.y, wv.y,
                     fmaf(m.z, wv.z,
                     fmaf(m.w, wv.w, acc[r]))));
        }
    }

    // reduce over kp (lane bits 0..2)
#pragma unroll
    for (int r = 0; r < 8; r++) {
        float v = acc[r];
        v += __shfl_xor_sync(0xffffffffu, v, 1);
        v += __shfl_xor_sync(0xffffffffu, v, 2);
        v += __shfl_xor_sync(0xffffffffu, v, 4);
        acc[r] = v;
    }
    if (kp == 0) {
        float bias = Wb[h];
#pragma unroll
        for (int r = 0; r < 8; r++)
            g_z[(s0 + r) * HH + h] = fmaxf(acc[r] + bias, 0.0f);
    }
}

// ---------------------------------------------------------------------------
// Kernel B1: per (b,c): score[s] = U_w[c,:].z[b,s,:]; softmax-exp; inclusive
// cumsum over s -> g_cumexp; e -> g_e. grid 16 = B*C, 128 threads.
// ---------------------------------------------------------------------------
__global__ void __launch_bounds__(128) kernelB1(const float* __restrict__ Uw)
{
    __shared__ float Ush[HH];
    __shared__ float wred[4];
    __shared__ float wsum[4];

    int b = blockIdx.x >> 3;
    int c = blockIdx.x & 7;
    int tid = threadIdx.x;
    int lane = tid & 31, w = tid >> 5;

    if (tid < 64)
        ((float4*)Ush)[tid] = ((const float4*)(Uw + c * HH))[tid];
    __syncthreads();

    // per-thread full dot (64 independent float4 loads -> high MLP)
    float sc = 0.0f;
    {
        const float4* zr = (const float4*)&g_z[(b * SS + tid) * HH];
        const float4* u4 = (const float4*)Ush;
#pragma unroll 8
        for (int k = 0; k < 64; k++) {
            float4 z = zr[k];
            float4 u = u4[k];
            sc += z.x * u.x + z.y * u.y + z.z * u.z + z.w * u.w;
        }
    }
    float m = sc;
#pragma unroll
    for (int o = 16; o > 0; o >>= 1)
        m = fmaxf(m, __shfl_xor_sync(0xffffffffu, m, o));
    if (lane == 0) wred[w] = m;
    __syncthreads();
    float mx = fmaxf(fmaxf(wred[0], wred[1]), fmaxf(wred[2], wred[3]));

    float e = expf(sc - mx);
    float x = e;
#pragma unroll
    for (int o = 1; o < 32; o <<= 1) {
        float t = __shfl_up_sync(0xffffffffu, x, o);
        if (lane >= o) x += t;
    }
    if (lane == 31) wsum[w] = x;
    __syncthreads();
    float pre = 0.0f;
    for (int ww = 0; ww < w; ww++) pre += wsum[ww];

    g_e[(b * CC + c) * SS + tid] = e;
    g_cumexp[(b * SS + tid) * CC + c] = x + pre;
}

// ---------------------------------------------------------------------------
// Kernel B2: g_cumm[b,s,c,h] = inclusive cumsum_s( memory[b,s,h] * e[b,c,s] )
// grid 128 = (b,c) x 8 h-chunks of 32; 256 threads = 32 h-lanes x 8 s-groups
// of 16. Per-thread running sum over 16 s, smem prefix over groups.
// ---------------------------------------------------------------------------
__global__ void __launch_bounds__(256) kernelB2(const float* __restrict__ memory)
{
    __shared__ float esh[SS];
    __shared__ float psum[8][32];

    int bid = blockIdx.x;
    int hc = bid & 7;
    int bc = bid >> 3;               // b*CC + c
    int b = bc >> 3;
    int c = bc & 7;
    int tid = threadIdx.x;
    int hl = tid & 31;
    int sg = tid >> 5;               // s-group 0..7

    if (tid < SS) esh[tid] = g_e[bc * SS + tid];
    __syncthreads();

    int h = hc * 32 + hl;
    const float* mp = memory + (size_t)b * SS * HH + h;

    float val[16];
    float run = 0.0f;
#pragma unroll
    for (int k = 0; k < 16; k++) {
        int s = sg * 16 + k;
        run = fmaf(mp[(size_t)s * HH], esh[s], run);
        val[k] = run;
    }
    psum[sg][hl] = run;
    __syncthreads();

    float off = 0.0f;
    for (int t = 0; t < sg; t++) off += psum[t][hl];

    float* op = g_cumm + ((size_t)b * SS * CC + c) * HH + h;
#pragma unroll
    for (int k = 0; k < 16; k++) {
        int s = sg * 16 + k;
        op[(size_t)s * (CC * HH)] = val[k] + off;
    }
}

// ---------------------------------------------------------------------------
// Main kernel:
//   out[b,i,j,c] = (sum_h relu(R[j,h]-P[i,h]) * V[c,h]) / denom + V_b[c]
// grid 256 = b(2) x i-tile(4 of 32) x j-tile(8 of 16) x c-pair(4); 256 thr.
// Single wave at occupancy 2. warps: 2 local c x 4 h-quarters.
// lanes: 8 ilane x 4 jlane; per-lane tile 4i x 4j (16 accumulators).
// ---------------------------------------------------------------------------
__global__ void __launch_bounds__(256, 2) kernelMain(const float* __restrict__ Vw,
                                                     const float* __restrict__ Vb,
                                                     float* __restrict__ out)
{
    extern __shared__ float sm[];
    float* Psh = sm;                   // 64 * PAD = 16640 (2c x 32 i-rows)
    float* Rsh = sm + 16640;           // 32 * PAD = 8320  (2c x 16 j-rows)
    float* Vsh = sm + 24960;           // 512   (total 25472 fl = 101888 B)
    float* red = sm;                   // aliases Psh; 8 x 544 = 4352 fl

    int bid = blockIdx.x;
    int cpair = bid & 3;
    int jt = (bid >> 2) & 7;
    int it = (bid >> 5) & 3;
    int b = bid >> 7;
    int i0 = it * 32, j0 = jt * 16, cbase = cpair * 2;
    int tid = threadIdx.x;

    // stage V (2 c x 256 h)
    if (tid < 128)
        *(float4*)&Vsh[tid * 4] = *(const float4*)&Vw[cbase * HH + tid * 4];

    // stage P: 64 rows (2c x 32), 8 threads/row, 2 passes
    {
        int c4 = tid & 7;
#pragma unroll
        for (int pass = 0; pass < 2; pass++) {
            int rr = (tid >> 3) + pass * 32;   // 0..63
            int cl = rr >> 5, ir = rr & 31;
            int gi = i0 + ir;
            const float* srcP = (gi == 0) ? (const float*)0
                : &g_cumm[((size_t)(b * SS + gi - 1) * CC + cbase + cl) * HH];
            float* dstP = &Psh[rr * PAD];
#pragma unroll
            for (int k = 0; k < 8; k++) {
                int h = c4 * 4 + k * 32;
                float4 pv = srcP ? *(const float4*)&srcP[h]
                                 : make_float4(0.f, 0.f, 0.f, 0.f);
                *(float4*)&dstP[h] = pv;
            }
        }
        // stage R: 32 rows (2c x 16), 1 pass
        int rr = tid >> 3;
        int cl = rr >> 4, jr = rr & 15;
        int gj = j0 + jr;
        const float* srcR = &g_cumm[((size_t)(b * SS + gj) * CC + cbase + cl) * HH];
        float* dstR = &Rsh[rr * PAD];
#pragma unroll
        for (int k = 0; k < 8; k++) {
            int h = c4 * 4 + k * 32;
            *(float4*)&dstR[h] = *(const float4*)&srcR[h];
        }
    }
    __syncthreads();

    int lane = tid & 31, w = tid >> 5;
    int cl = w & 1;                    // local c
    int hq = w >> 1;                   // h quarter 0..3
    int ilane = lane >> 2;             // 0..7
    int jlane = lane & 3;              // 0..3

    const float* Pb = &Psh[(cl * 32) * PAD];
    const float* Rb = &Rsh[(cl * 16) * PAD];
    const float* Vp = &Vsh[cl * HH];

    float acc[4][4];
#pragma unroll
    for (int ii = 0; ii < 4; ii++)
#pragma unroll
        for (int jj = 0; jj < 4; jj++) acc[ii][jj] = 0.0f;

    int hbase = hq * 64;
#pragma unroll 4
    for (int hh = 0; hh < 64; hh += 4) {
        int h = hbase + hh;
        float4 v = *(const float4*)&Vp[h];
        float4 p[4];
#pragma unroll
        for (int ii = 0; ii < 4; ii++)
            p[ii] = *(const float4*)&Pb[(ilane + 8 * ii) * PAD + h];
#pragma unroll
        for (int jj = 0; jj < 4; jj++) {
            float4 r = *(const float4*)&Rb[(jlane + 4 * jj) * PAD + h];
#pragma unroll
            for (int ii = 0; ii < 4; ii++) {
                float t;
                t = fmaxf(r.x - p[ii].x, 0.0f); acc[ii][jj] = fmaf(t, v.x, acc[ii][jj]);
                t = fmaxf(r.y - p[ii].y, 0.0f); acc[ii][jj] = fmaf(t, v.y, acc[ii][jj]);
                t = fmaxf(r.z - p[ii].z, 0.0f); acc[ii][jj] = fmaf(t, v.z, acc[ii][jj]);
                t = fmaxf(r.w - p[ii].w, 0.0f); acc[ii][jj] = fmaf(t, v.w, acc[ii][jj]);
            }
        }
    }

    __syncthreads();   // all warps done reading Psh before red overwrites it

    // partials: red[(hq*2+cl)*544 + i*17 + j]
#pragma unroll
    for (int ii = 0; ii < 4; ii++)
#pragma unroll
        for (int jj = 0; jj < 4; jj++) {
            int i = ilane + 8 * ii;
            int j = jlane + 4 * jj;
            red[(hq * 2 + cl) * 544 + i * 17 + j] = acc[ii][jj];
        }
    __syncthreads();

    // epilogue: thread tid handles (c0,c1) for (i, j) and (i+16, j)
    {
        int i = tid >> 4;              // 0..15
        int j = tid & 15;
#pragma unroll
        for (int rep = 0; rep < 2; rep++) {
            int ir = i + 16 * rep;
            int o = ir * 17 + j;
            float s0 = red[o] + red[1088 + o] + red[2176 + o] + red[3264 + o];
            int o2 = o + 544;
            float s1 = red[o2] + red[1088 + o2] + red[2176 + o2] + red[3264 + o2];
            int gi = i0 + ir, gj = j0 + j;
            float cej0 = g_cumexp[(b * SS + gj) * CC + cbase];
            float cej1 = g_cumexp[(b * SS + gj) * CC + cbase + 1];
            float cei0 = 0.0f, cei1 = 0.0f;
            if (gi > 0) {
                cei0 = g_cumexp[(b * SS + gi - 1) * CC + cbase];
                cei1 = g_cumexp[(b * SS + gi - 1) * CC + cbase + 1];
            }
            float d0 = cej0 - cei0; if (d0 <= 1e-6f) d0 = 100.0f;
            float d1 = cej1 - cei1; if (d1 <= 1e-6f) d1 = 100.0f;
            float2 res;
            res.x = __fdividef(s0, d0) + Vb[cbase];
            res.y = __fdividef(s1, d1) + Vb[cbase + 1];
            *(float2*)&out[((size_t)(b * SS + gi) * SS + gj) * CC + cbase] = res;
        }
    }
}

// ---------------------------------------------------------------------------
extern "C" void kernel_launch(void* const* d_in, const int* in_sizes, int n_in,
                              void* d_out, int out_size)
{
    (void)in_sizes; (void)n_in; (void)out_size;
    const float* memory = (const float*)d_in[0];
    const float* Ww     = (const float*)d_in[1];
    const float* Wb     = (const float*)d_in[2];
    const float* Uw     = (const float*)d_in[3];
    const float* Vw     = (const float*)d_in[4];
    const float* Vb     = (const float*)d_in[5];
    float* out          = (float*)d_out;

    cudaFuncSetAttribute(kernelMain, cudaFuncAttributeMaxDynamicSharedMemorySize,
                         25472 * 4);

    kernelA<<<256, 256>>>(memory, Ww, Wb);
    kernelB1<<<16, 128>>>(Uw);
    kernelB2<<<128, 256>>>(memory);
    kernelMain<<<256, 256, 25472 * 4>>>(Vw, Vb, out);
}